// round 5
// baseline (speedup 1.0000x reference)
#include <cuda_runtime.h>
#include <math.h>

// Problem constants
constexpr int BATCH = 128;
constexpr int SEQT  = 24;
constexpr int EMB   = 512;
constexpr int HID   = 1024;
constexpr int VOC   = 12000;
constexpr int MALL  = SEQT * BATCH;   // 3072 (row m = t*128 + b)
constexpr int G4    = 4 * HID;        // 4096

// Scratch (device globals: allocation is forbidden)
__device__ float g_xall[(size_t)MALL * EMB];   // gathered inputs  [3072, 512]   6.3 MB
__device__ float g_gpre[(size_t)MALL * G4];    // input-proj gates [3072, 4096] 50.3 MB
__device__ float g_allh[(size_t)MALL * HID];   // all hidden states[3072, 1024] 12.6 MB
__device__ float g_cbuf[2 * BATCH * HID];      // double-buffered cell state     1.0 MB

// ---------------------------------------------------------------------------
// Gather: X_all[t*128+b] = (t==0) ? encoder_output[b] : embed_table[captions[b][t-1]]
// ---------------------------------------------------------------------------
__global__ void gather_x_kernel(const float* __restrict__ enc,
                                const int*   __restrict__ caps,
                                const float* __restrict__ emb)
{
    const int m = blockIdx.x;          // 0..3071
    const int t = m >> 7;
    const int b = m & 127;
    const float* src = (t == 0)
        ? (enc + (size_t)b * EMB)
        : (emb + (size_t)caps[b * SEQT + (t - 1)] * EMB);
    float4* dst = reinterpret_cast<float4*>(g_xall + (size_t)m * EMB);
    dst[threadIdx.x] = reinterpret_cast<const float4*>(src)[threadIdx.x];  // 128 thr * 4 = 512
}

// ---------------------------------------------------------------------------
// SGEMM: C[M,N] = A[M,K] @ W[N,K]^T (+ b1 + b2)
//   128x128 tile, BK=8, 256 threads, 8x8 per-thread (split 4+4 for coalescing)
//   mode 0: C row-major [M,N]
//   mode 1: FC epilogue — m = t*128+b, write C[(b*SEQT+t)*N + n]
// ---------------------------------------------------------------------------
__global__ void __launch_bounds__(256)
sgemm_nt_kernel(const float* __restrict__ A, const float* __restrict__ Wt,
                const float* __restrict__ b1, const float* __restrict__ b2,
                float* __restrict__ C, int M, int N, int K, int mode)
{
    __shared__ float As[8][128];
    __shared__ float Ws[8][128];

    const int tid = threadIdx.x;
    const int m0 = blockIdx.y * 128;
    const int n0 = blockIdx.x * 128;
    const int lr = tid >> 1;            // load row in tile 0..127
    const int lc = (tid & 1) * 4;       // load k offset 0/4
    const int tx = tid & 15;            // col thread 0..15
    const int ty = tid >> 4;            // row thread 0..15

    float acc[8][8];
#pragma unroll
    for (int i = 0; i < 8; i++)
#pragma unroll
        for (int j = 0; j < 8; j++) acc[i][j] = 0.f;

    const float* aPtr = A + (size_t)(m0 + lr) * K + lc;       // M always %128==0
    const bool wOk = (n0 + lr) < N;
    const float* wPtr = Wt + (size_t)(wOk ? (n0 + lr) : 0) * K + lc;

    for (int k0 = 0; k0 < K; k0 += 8) {
        const float4 av = *reinterpret_cast<const float4*>(aPtr + k0);
        float4 wv = make_float4(0.f, 0.f, 0.f, 0.f);
        if (wOk) wv = *reinterpret_cast<const float4*>(wPtr + k0);
        As[lc + 0][lr] = av.x; As[lc + 1][lr] = av.y;
        As[lc + 2][lr] = av.z; As[lc + 3][lr] = av.w;
        Ws[lc + 0][lr] = wv.x; Ws[lc + 1][lr] = wv.y;
        Ws[lc + 2][lr] = wv.z; Ws[lc + 3][lr] = wv.w;
        __syncthreads();
#pragma unroll
        for (int kk = 0; kk < 8; kk++) {
            float a[8], w[8];
            *reinterpret_cast<float4*>(&a[0]) = *reinterpret_cast<const float4*>(&As[kk][ty * 4]);
            *reinterpret_cast<float4*>(&a[4]) = *reinterpret_cast<const float4*>(&As[kk][64 + ty * 4]);
            *reinterpret_cast<float4*>(&w[0]) = *reinterpret_cast<const float4*>(&Ws[kk][tx * 4]);
            *reinterpret_cast<float4*>(&w[4]) = *reinterpret_cast<const float4*>(&Ws[kk][64 + tx * 4]);
#pragma unroll
            for (int i = 0; i < 8; i++)
#pragma unroll
                for (int j = 0; j < 8; j++)
                    acc[i][j] = fmaf(a[i], w[j], acc[i][j]);
        }
        __syncthreads();
    }

#pragma unroll
    for (int ih = 0; ih < 2; ih++)
#pragma unroll
        for (int i2 = 0; i2 < 4; i2++) {
            const int i = ih * 4 + i2;
            const int m = m0 + ih * 64 + ty * 4 + i2;
            size_t rowBase;
            if (mode == 0) {
                rowBase = (size_t)m * N;
            } else {
                const int tt = m >> 7, bb = m & 127;
                rowBase = ((size_t)bb * SEQT + tt) * N;
            }
#pragma unroll
            for (int jh = 0; jh < 2; jh++) {
                const int n = n0 + jh * 64 + tx * 4;
                if (n >= N) continue;   // N%4==0, n 4-aligned -> whole float4 valid
                float4 v;
                v.x = acc[i][jh * 4 + 0];
                v.y = acc[i][jh * 4 + 1];
                v.z = acc[i][jh * 4 + 2];
                v.w = acc[i][jh * 4 + 3];
                if (b1) { v.x += b1[n]; v.y += b1[n + 1]; v.z += b1[n + 2]; v.w += b1[n + 3]; }
                if (b2) { v.x += b2[n]; v.y += b2[n + 1]; v.z += b2[n + 2]; v.w += b2[n + 3]; }
                *reinterpret_cast<float4*>(C + rowBase + n) = v;
            }
        }
}

// ---------------------------------------------------------------------------
// Recurrent step t: for n-columns [n0, n0+8) x 4 gates:
//   gates = G_pre[t] + h_{t-1} @ W_hh^T ; then fused LSTM cell update.
//   h_{t-1} read from g_allh[t-1] (zeros at t==0), c double-buffered in g_cbuf.
//   Grid: 128 blocks x 128 threads. Per block: C[128,32] += H[128,1024]@Wsel^T.
// ---------------------------------------------------------------------------
__global__ void __launch_bounds__(128)
lstm_step_kernel(const float* __restrict__ Whh, int t)
{
    __shared__ float Hs[16][128];      // 8 KB
    __shared__ float Ws[16][36];       // 2.3 KB (padded)
    __shared__ float Cs[128][33];      // 16.9 KB (padded -> conflict-free epilogue)

    const int tid = threadIdx.x;
    const int n0 = blockIdx.x * 8;

    float acc[8][4];
#pragma unroll
    for (int i = 0; i < 8; i++)
#pragma unroll
        for (int j = 0; j < 4; j++) acc[i][j] = 0.f;

    const int rg = tid >> 3;   // row group 0..15  -> rows rg*8..rg*8+7
    const int cg = tid & 7;    // col group 0..7   -> cols cg*4..cg*4+3

    if (t > 0) {
        const float* hprev = g_allh + (size_t)(t - 1) * BATCH * HID;
        const int hr = tid >> 2;            // 0..31
        const int hk = (tid & 3) * 4;       // 0/4/8/12
        const int wc = tid >> 2;            // smem gate-col 0..31  (= gate*8 + j)
        const int wk = (tid & 3) * 4;
        const int wgate = wc >> 3, wj = wc & 7;
        const float* wrow = Whh + (size_t)(wgate * HID + n0 + wj) * HID;

        for (int k0 = 0; k0 < HID; k0 += 16) {
#pragma unroll
            for (int p = 0; p < 4; p++) {
                const int r = p * 32 + hr;
                const float4 v = *reinterpret_cast<const float4*>(hprev + (size_t)r * HID + k0 + hk);
                Hs[hk + 0][r] = v.x; Hs[hk + 1][r] = v.y;
                Hs[hk + 2][r] = v.z; Hs[hk + 3][r] = v.w;
            }
            {
                const float4 w = *reinterpret_cast<const float4*>(wrow + k0 + wk);
                Ws[wk + 0][wc] = w.x; Ws[wk + 1][wc] = w.y;
                Ws[wk + 2][wc] = w.z; Ws[wk + 3][wc] = w.w;
            }
            __syncthreads();
#pragma unroll
            for (int kk = 0; kk < 16; kk++) {
                float a[8], w4[4];
                *reinterpret_cast<float4*>(&a[0]) = *reinterpret_cast<const float4*>(&Hs[kk][rg * 8]);
                *reinterpret_cast<float4*>(&a[4]) = *reinterpret_cast<const float4*>(&Hs[kk][rg * 8 + 4]);
                *reinterpret_cast<float4*>(&w4[0]) = *reinterpret_cast<const float4*>(&Ws[kk][cg * 4]);
#pragma unroll
                for (int i = 0; i < 8; i++)
#pragma unroll
                    for (int j = 0; j < 4; j++)
                        acc[i][j] = fmaf(a[i], w4[j], acc[i][j]);
            }
            __syncthreads();
        }
    }

    // Stage GEMM tile to smem so each thread owns one batch row for the cell update
#pragma unroll
    for (int i = 0; i < 8; i++)
#pragma unroll
        for (int j = 0; j < 4; j++)
            Cs[rg * 8 + i][cg * 4 + j] = acc[i][j];
    __syncthreads();

    const int b = tid;  // one thread per batch row
    const float* gpre = g_gpre + ((size_t)t * BATCH + b) * G4;
    float pre[4][8];
#pragma unroll
    for (int g = 0; g < 4; g++) {
        *reinterpret_cast<float4*>(&pre[g][0]) = *reinterpret_cast<const float4*>(gpre + g * HID + n0);
        *reinterpret_cast<float4*>(&pre[g][4]) = *reinterpret_cast<const float4*>(gpre + g * HID + n0 + 4);
    }
    float cold[8];
    if (t > 0) {
        const float* cprev = g_cbuf + (size_t)(t & 1) * BATCH * HID + (size_t)b * HID;
        *reinterpret_cast<float4*>(&cold[0]) = *reinterpret_cast<const float4*>(cprev + n0);
        *reinterpret_cast<float4*>(&cold[4]) = *reinterpret_cast<const float4*>(cprev + n0 + 4);
    } else {
#pragma unroll
        for (int j = 0; j < 8; j++) cold[j] = 0.f;
    }
    float* cnext = g_cbuf + (size_t)((t + 1) & 1) * BATCH * HID + (size_t)b * HID;
    float* hout  = g_allh + ((size_t)t * BATCH + b) * HID;

    float hn[8], cn[8];
#pragma unroll
    for (int j = 0; j < 8; j++) {
        const float gi = 1.f / (1.f + expf(-(Cs[b][0  + j] + pre[0][j])));
        const float gf = 1.f / (1.f + expf(-(Cs[b][8  + j] + pre[1][j])));
        const float gg = tanhf(Cs[b][16 + j] + pre[2][j]);
        const float go = 1.f / (1.f + expf(-(Cs[b][24 + j] + pre[3][j])));
        const float cv = gf * cold[j] + gi * gg;
        cn[j] = cv;
        hn[j] = go * tanhf(cv);
    }
    *reinterpret_cast<float4*>(cnext + n0)     = *reinterpret_cast<float4*>(&cn[0]);
    *reinterpret_cast<float4*>(cnext + n0 + 4) = *reinterpret_cast<float4*>(&cn[4]);
    *reinterpret_cast<float4*>(hout + n0)      = *reinterpret_cast<float4*>(&hn[0]);
    *reinterpret_cast<float4*>(hout + n0 + 4)  = *reinterpret_cast<float4*>(&hn[4]);
}

// ---------------------------------------------------------------------------
// Launch: gather -> input GEMM -> 24 recurrent steps -> FC GEMM (reordered out)
// ---------------------------------------------------------------------------
extern "C" void kernel_launch(void* const* d_in, const int* in_sizes, int n_in,
                              void* d_out, int out_size)
{
    const float* enc = (const float*)d_in[0];   // [128, 512]
    const int*   caps= (const int*  )d_in[1];   // [128, 24]
    const float* emb = (const float*)d_in[2];   // [12000, 512]
    const float* Wih = (const float*)d_in[3];   // [4096, 512]
    const float* Whh = (const float*)d_in[4];   // [4096, 1024]
    const float* bih = (const float*)d_in[5];   // [4096]
    const float* bhh = (const float*)d_in[6];   // [4096]
    const float* Wfc = (const float*)d_in[7];   // [12000, 1024]
    const float* bfc = (const float*)d_in[8];   // [12000]
    float* out = (float*)d_out;                 // [128, 24, 12000]

    float *xall = nullptr, *gpre = nullptr, *allh = nullptr;
    cudaGetSymbolAddress((void**)&xall, g_xall);
    cudaGetSymbolAddress((void**)&gpre, g_gpre);
    cudaGetSymbolAddress((void**)&allh, g_allh);

    // 1) gather all teacher-forced inputs
    gather_x_kernel<<<MALL, 128>>>(enc, caps, emb);

    // 2) batched input projection: G_pre = X_all @ W_ih^T + (b_ih + b_hh)
    sgemm_nt_kernel<<<dim3(G4 / 128, MALL / 128), 256>>>(
        xall, Wih, bih, bhh, gpre, MALL, G4, EMB, 0);

    // 3) sequential recurrence (only h @ W_hh^T per step)
    for (int t = 0; t < SEQT; t++)
        lstm_step_kernel<<<HID / 8, 128>>>(Whh, t);

    // 4) final FC with [b][t][v] reorder + bias
    sgemm_nt_kernel<<<dim3((VOC + 127) / 128, MALL / 128), 256>>>(
        allh, Wfc, bfc, nullptr, out, MALL, VOC, HID, 1);
}